// round 11
// baseline (speedup 1.0000x reference)
#include <cuda_runtime.h>
#include <float.h>
#include <math.h>

// Problem constants (from reference)
#define BEV_N   200          // BEV_H == BEV_W == 200
#define IMG_H   128
#define IMG_W   352
#define NCH     32
#define NB      2            // batch
#define NCAM    6            // cameras per batch
#define BNMAT   (NB*NCAM)    // 12 projection matrices
#define NPOS    (BEV_N*BEV_N)       // 40,000 positions (per batch)
#define NTASKS  (NPOS / 4)          // 10,000 warp-tasks (4 positions each)
#define THREADS 256
#define WARPS_PER_BLOCK (THREADS/32)
#define NBLOCKS 296                  // 2 * 148 SMs
#define TOTAL_WARPS (NBLOCKS * WARPS_PER_BLOCK)   // 2368
#define ROWSTRIDE (IMG_W * (NCH/4))
#define GRID_STEP 0.50251256281407031975f   // 100/199 rounded to fp32

// Persistent warp-centric kernel. Each warp grid-strides over 4-position tasks;
// per task it handles both batches' cells at those positions. All per-task state
// is warp-local (smem slots owned by the warp, __syncwarp only), so successive
// tasks overlap in the scoreboard: next task's projection math issues while the
// previous task's gathers are in flight.
__global__ __launch_bounds__(THREADS) void ipm_fused_kernel(const float* __restrict__ images,
                                                            const float* __restrict__ Ks,
                                                            const float* __restrict__ RTs,
                                                            float* __restrict__ out) {
    __shared__ float  sP[BNMAT][9];
    __shared__ float4 sW[WARPS_PER_BLOCK * 4][NB][NCAM];    // per (warp,pos)
    __shared__ int    sBase[WARPS_PER_BLOCK * 4][NB][NCAM];

    const int t = threadIdx.x;

    // ---------- Phase 0 (once per block): projection matrices ----------
    if (t < BNMAT * 9) {
        const int m  = t / 9;
        const int e  = t - m * 9;
        const int r  = e / 3;
        const int ci = e - r * 3;
        const int c  = (ci == 2) ? 3 : ci;
        const float* K  = Ks  + m * 16 + r * 4;
        const float* RT = RTs + m * 16;
        sP[m][e] = K[0] * RT[c] + K[1] * RT[4 + c]
                 + K[2] * RT[8 + c] + K[3] * RT[12 + c];
    }
    __syncthreads();

    const int warpId = t >> 5;
    const int lane   = t & 31;
    const int lpos   = lane >> 3;                      // position-in-task 0..3
    const int sub    = lane & 7;                       // lane-in-position / cam slot
    const int wpos   = warpId * 4 + lpos;              // this thread's smem row
    const int gwarp  = blockIdx.x * WARPS_PER_BLOCK + warpId;

    const float4* __restrict__ img4 = (const float4*)images;
    float4* __restrict__ out4 = (float4*)out;
    const float4 zero4 = make_float4(0.f, 0.f, 0.f, 0.f);

    for (int task = gwarp; task < NTASKS; task += TOTAL_WARPS) {
        const int p = task * 4 + lpos;                 // global BEV position
        const int i = p / BEV_N;
        const int j = p - i * BEV_N;
        // linspace(-50,50,200) in fp32 (<=1 ulp vs numpy's f64->f32; NO fp64 pipe)
        const float y = fmaf((float)i, GRID_STEP, -50.0f);
        const float x = fmaf((float)j, GRID_STEP, -50.0f);

        // ---------- Phase 1: project both batches + warp-local compaction ----------
        int nA, nB;
        {
            const int cam = sub;                       // cams 0..5 active, 6..7 idle
            bool vA = false, vB = false;
            float4 wA = zero4, wB = zero4;
            int bA = 0, bB = 0;

            if (cam < NCAM) {
                #pragma unroll
                for (int ba = 0; ba < NB; ba++) {
                    const int bn = ba * NCAM + cam;
                    const float* P = sP[bn];
                    const float pc0 = P[0] * y + P[1] * x + P[2];
                    const float pc1 = P[3] * y + P[4] * x + P[5];
                    const float pc2 = P[6] * y + P[7] * x + P[8];
                    const float inv = 1.0f / (pc2 + 1e-7f);
                    const float fx = pc0 * inv;
                    const float fy = pc1 * inv;
                    // Outside [0,W-1) x [0,H-1): clamped bilinear collapses => exact 0
                    if (fx >= 0.0f && fx < (float)(IMG_W - 1) &&
                        fy >= 0.0f && fy < (float)(IMG_H - 1)) {
                        const float x0f = floorf(fx);
                        const float y0f = floorf(fy);
                        const float wx1 = fx - x0f, wx0 = 1.0f - wx1;
                        const float wy1 = fy - y0f, wy0 = 1.0f - wy1;
                        const float4 w = make_float4(wx0 * wy0, wx0 * wy1,
                                                     wx1 * wy0, wx1 * wy1);
                        const int base = ((bn * IMG_H + (int)y0f) * IMG_W + (int)x0f) * (NCH / 4);
                        if (ba == 0) { vA = true; wA = w; bA = base; }
                        else         { vB = true; wB = w; bB = base; }
                    }
                }
            }

            const unsigned ballA = __ballot_sync(0xFFFFFFFFu, vA);
            const unsigned ballB = __ballot_sync(0xFFFFFFFFu, vB);
            const int laneBase   = lane & ~7;                   // first lane of 8-group
            const unsigned grpA  = (ballA >> laneBase) & 0xFFu;
            const unsigned grpB  = (ballB >> laneBase) & 0xFFu;
            const unsigned below = (1u << sub) - 1u;
            if (vA) {
                const int slot = __popc(grpA & below);          // cam-ordered slot
                sW[wpos][0][slot] = wA;  sBase[wpos][0][slot] = bA;
            }
            if (vB) {
                const int slot = __popc(grpB & below);
                sW[wpos][1][slot] = wB;  sBase[wpos][1][slot] = bB;
            }
            nA = (int)__popc(grpA);
            nB = (int)__popc(grpB);
        }
        __syncwarp();   // phase 1 writes / phase 2 reads are warp-local

        // ---------- Phase 2: branchless paired sampling, max-reduce ----------
        // If every cam is valid the result is max over the 6 samples; otherwise
        // some cam contributes an exact 0 (clamp-collapsed weights) -> seed 0.
        float4 bestA = (nA == NCAM)
            ? make_float4(-FLT_MAX, -FLT_MAX, -FLT_MAX, -FLT_MAX)
            : zero4;
        float4 bestB = (nB == NCAM)
            ? make_float4(-FLT_MAX, -FLT_MAX, -FLT_MAX, -FLT_MAX)
            : zero4;

        const int nmax = (nA > nB) ? nA : nB;

        #pragma unroll 1
        for (int k = 0; k < nmax; k++) {
            const bool okA = (k < nA), okB = (k < nB);
            const int  kA  = okA ? k : 0, kB = okB ? k : 0;
            // Inactive side: weight := 0 (exact-zero contribution), base := 0 (safe)
            float4 wA = sW[wpos][0][kA];  int baA = okA ? sBase[wpos][0][kA] : 0;
            float4 wB = sW[wpos][1][kB];  int baB = okB ? sBase[wpos][1][kB] : 0;
            if (!okA) wA = zero4;
            if (!okB) wB = zero4;

            const float4* pa = img4 + baA + sub;
            const float4* pb = img4 + baB + sub;
            // 8 independent loads in flight before any consume
            const float4 a00 = __ldg(pa);
            const float4 a10 = __ldg(pa + (NCH / 4));
            const float4 a01 = __ldg(pa + ROWSTRIDE);
            const float4 a11 = __ldg(pa + ROWSTRIDE + (NCH / 4));
            const float4 b00 = __ldg(pb);
            const float4 b10 = __ldg(pb + (NCH / 4));
            const float4 b01 = __ldg(pb + ROWSTRIDE);
            const float4 b11 = __ldg(pb + ROWSTRIDE + (NCH / 4));

            float4 v;
            v.x = wA.x * a00.x + wA.y * a01.x + wA.z * a10.x + wA.w * a11.x;
            v.y = wA.x * a00.y + wA.y * a01.y + wA.z * a10.y + wA.w * a11.y;
            v.z = wA.x * a00.z + wA.y * a01.z + wA.z * a10.z + wA.w * a11.z;
            v.w = wA.x * a00.w + wA.y * a01.w + wA.z * a10.w + wA.w * a11.w;
            bestA.x = fmaxf(bestA.x, v.x);
            bestA.y = fmaxf(bestA.y, v.y);
            bestA.z = fmaxf(bestA.z, v.z);
            bestA.w = fmaxf(bestA.w, v.w);

            v.x = wB.x * b00.x + wB.y * b01.x + wB.z * b10.x + wB.w * b11.x;
            v.y = wB.x * b00.y + wB.y * b01.y + wB.z * b10.y + wB.w * b11.y;
            v.z = wB.x * b00.z + wB.y * b01.z + wB.z * b10.z + wB.w * b11.z;
            v.w = wB.x * b00.w + wB.y * b01.w + wB.z * b10.w + wB.w * b11.w;
            bestB.x = fmaxf(bestB.x, v.x);
            bestB.y = fmaxf(bestB.y, v.y);
            bestB.z = fmaxf(bestB.z, v.z);
            bestB.w = fmaxf(bestB.w, v.w);
        }

        out4[(size_t)p * (NCH / 4) + sub]          = bestA;   // batch 0 cell
        out4[(size_t)(NPOS + p) * (NCH / 4) + sub] = bestB;   // batch 1 cell

        __syncwarp();   // protect smem slots from next iteration's overwrite
    }
}

extern "C" void kernel_launch(void* const* d_in, const int* in_sizes, int n_in,
                              void* d_out, int out_size) {
    const float* images = (const float*)d_in[0];
    const float* Ks     = (const float*)d_in[1];
    const float* RTs    = (const float*)d_in[2];
    float* out = (float*)d_out;

    ipm_fused_kernel<<<NBLOCKS, THREADS>>>(images, Ks, RTs, out);
}

// round 12
// speedup vs baseline: 1.4412x; 1.4412x over previous
#include <cuda_runtime.h>
#include <float.h>
#include <math.h>

// Problem constants (from reference)
#define BEV_N   200          // BEV_H == BEV_W == 200
#define IMG_H   128
#define IMG_W   352
#define NCH     32
#define NB      2            // batch
#define NCAM    6            // cameras per batch
#define BNMAT   (NB*NCAM)    // 12 projection matrices
#define NPOS    (BEV_N*BEV_N)       // 40,000 positions (per batch)
#define POS_PER_BLOCK 16            // 128 threads / 8 lanes-per-position
#define NBLOCKS (NPOS / POS_PER_BLOCK)   // 2500
#define ROWSTRIDE (IMG_W * (NCH/4))
#define GRID_STEP 0.50251256281407031975f   // 100/199 rounded to fp32

// One fused kernel. Each thread owns ONE position but BOTH batches' cells.
// Work mapping: warp w of block b covers positions 4*(w*NBLOCKS + b)..+3.
//  - intra-warp: 4 CONSECUTIVE positions -> gathers within a warp hit adjacent
//    image lines (the locality that R9 showed is essential)
//  - inter-warp: a block's 4 warps are spread across the BEV -> block duration
//    ~= mean work, no straggler blocks in the single-wave launch
__global__ __launch_bounds__(128) void ipm_fused_kernel(const float* __restrict__ images,
                                                        const float* __restrict__ Ks,
                                                        const float* __restrict__ RTs,
                                                        float* __restrict__ out) {
    __shared__ float  sP[BNMAT][9];
    __shared__ float4 sW[POS_PER_BLOCK][NB][NCAM];    // (w00,w01,w10,w11)
    __shared__ int    sBase[POS_PER_BLOCK][NB][NCAM]; // float4-index of im00 (pixel base)

    const int t = threadIdx.x;

    // ---------- Phase 0: projection matrices ----------
    if (t < BNMAT * 9) {
        const int m  = t / 9;
        const int e  = t - m * 9;
        const int r  = e / 3;
        const int ci = e - r * 3;
        const int c  = (ci == 2) ? 3 : ci;
        const float* K  = Ks  + m * 16 + r * 4;
        const float* RT = RTs + m * 16;
        sP[m][e] = K[0] * RT[c] + K[1] * RT[4 + c]
                 + K[2] * RT[8 + c] + K[3] * RT[12 + c];
    }
    __syncthreads();

    const int pos  = t >> 3;                           // local position slot 0..15
    const int sub  = t & 7;                            // lane-in-position / cam slot
    const int warp = t >> 5;                           // warp-in-block 0..3
    const int lpos = (t >> 3) & 3;                     // position-in-warp 0..3

    // Balanced warp-task mapping: 4 consecutive positions per warp,
    // warps of one block spread stride-NBLOCKS across the BEV.
    const int p = (warp * NBLOCKS + blockIdx.x) * 4 + lpos;

    const int i = p / BEV_N;
    const int j = p - i * BEV_N;
    // linspace(-50,50,200) in fp32 (<=1 ulp vs numpy's f64->f32; NO fp64 pipe)
    const float y = fmaf((float)i, GRID_STEP, -50.0f);
    const float x = fmaf((float)j, GRID_STEP, -50.0f);

    // ---------- Phase 1: project both batches + warp-local compaction ----------
    int nA, nB;
    {
        const int cam = sub;                           // cams 0..5 active, 6..7 idle
        bool vA = false, vB = false;
        float4 wA = make_float4(0.f, 0.f, 0.f, 0.f), wB = wA;
        int bA = 0, bB = 0;

        if (cam < NCAM) {
            #pragma unroll
            for (int ba = 0; ba < NB; ba++) {
                const int bn = ba * NCAM + cam;
                const float* P = sP[bn];
                const float pc0 = P[0] * y + P[1] * x + P[2];
                const float pc1 = P[3] * y + P[4] * x + P[5];
                const float pc2 = P[6] * y + P[7] * x + P[8];
                const float inv = 1.0f / (pc2 + 1e-7f);
                const float fx = pc0 * inv;
                const float fy = pc1 * inv;
                // Outside [0,W-1) x [0,H-1): clamped bilinear collapses => exact 0
                if (fx >= 0.0f && fx < (float)(IMG_W - 1) &&
                    fy >= 0.0f && fy < (float)(IMG_H - 1)) {
                    const float x0f = floorf(fx);
                    const float y0f = floorf(fy);
                    const float wx1 = fx - x0f, wx0 = 1.0f - wx1;
                    const float wy1 = fy - y0f, wy0 = 1.0f - wy1;
                    const float4 w = make_float4(wx0 * wy0, wx0 * wy1,
                                                 wx1 * wy0, wx1 * wy1);
                    const int base = ((bn * IMG_H + (int)y0f) * IMG_W + (int)x0f) * (NCH / 4);
                    if (ba == 0) { vA = true; wA = w; bA = base; }
                    else         { vB = true; wB = w; bB = base; }
                }
            }
        }

        const unsigned ballA = __ballot_sync(0xFFFFFFFFu, vA);
        const unsigned ballB = __ballot_sync(0xFFFFFFFFu, vB);
        const int laneBase   = (t & 31) & ~7;                   // first lane of 8-group
        const unsigned grpA  = (ballA >> laneBase) & 0xFFu;
        const unsigned grpB  = (ballB >> laneBase) & 0xFFu;
        const unsigned below = (1u << sub) - 1u;
        if (vA) {
            const int slot = __popc(grpA & below);              // cam-ordered slot
            sW[pos][0][slot] = wA;  sBase[pos][0][slot] = bA;
        }
        if (vB) {
            const int slot = __popc(grpB & below);
            sW[pos][1][slot] = wB;  sBase[pos][1][slot] = bB;
        }
        nA = (int)__popc(grpA);
        nB = (int)__popc(grpB);
    }
    __syncwarp();   // phase 1 writes / phase 2 reads are warp-local (same positions)

    // ---------- Phase 2: branchless paired sampling, max-reduce ----------
    // If every cam is valid the result is max over the 6 samples; otherwise some
    // cam contributes an exact 0 (clamp-collapsed weights), so seed with 0.
    float4 bestA = (nA == NCAM)
        ? make_float4(-FLT_MAX, -FLT_MAX, -FLT_MAX, -FLT_MAX)
        : make_float4(0.f, 0.f, 0.f, 0.f);
    float4 bestB = (nB == NCAM)
        ? make_float4(-FLT_MAX, -FLT_MAX, -FLT_MAX, -FLT_MAX)
        : make_float4(0.f, 0.f, 0.f, 0.f);

    const float4* __restrict__ img4 = (const float4*)images;
    const int nmax = (nA > nB) ? nA : nB;
    const float4 zero4 = make_float4(0.f, 0.f, 0.f, 0.f);

    #pragma unroll 1
    for (int k = 0; k < nmax; k++) {
        const bool okA = (k < nA), okB = (k < nB);
        const int  kA  = okA ? k : 0, kB = okB ? k : 0;
        // Inactive side: weight := 0 (exact-zero contribution), base := 0 (safe addr)
        float4 wA = sW[pos][0][kA];  int baA = okA ? sBase[pos][0][kA] : 0;
        float4 wB = sW[pos][1][kB];  int baB = okB ? sBase[pos][1][kB] : 0;
        if (!okA) wA = zero4;
        if (!okB) wB = zero4;

        const float4* pa = img4 + baA + sub;
        const float4* pb = img4 + baB + sub;
        // 8 independent loads in flight before any consume
        const float4 a00 = __ldg(pa);
        const float4 a10 = __ldg(pa + (NCH / 4));
        const float4 a01 = __ldg(pa + ROWSTRIDE);
        const float4 a11 = __ldg(pa + ROWSTRIDE + (NCH / 4));
        const float4 b00 = __ldg(pb);
        const float4 b10 = __ldg(pb + (NCH / 4));
        const float4 b01 = __ldg(pb + ROWSTRIDE);
        const float4 b11 = __ldg(pb + ROWSTRIDE + (NCH / 4));

        float4 v;
        v.x = wA.x * a00.x + wA.y * a01.x + wA.z * a10.x + wA.w * a11.x;
        v.y = wA.x * a00.y + wA.y * a01.y + wA.z * a10.y + wA.w * a11.y;
        v.z = wA.x * a00.z + wA.y * a01.z + wA.z * a10.z + wA.w * a11.z;
        v.w = wA.x * a00.w + wA.y * a01.w + wA.z * a10.w + wA.w * a11.w;
        bestA.x = fmaxf(bestA.x, v.x);
        bestA.y = fmaxf(bestA.y, v.y);
        bestA.z = fmaxf(bestA.z, v.z);
        bestA.w = fmaxf(bestA.w, v.w);

        v.x = wB.x * b00.x + wB.y * b01.x + wB.z * b10.x + wB.w * b11.x;
        v.y = wB.x * b00.y + wB.y * b01.y + wB.z * b10.y + wB.w * b11.y;
        v.z = wB.x * b00.z + wB.y * b01.z + wB.z * b10.z + wB.w * b11.z;
        v.w = wB.x * b00.w + wB.y * b01.w + wB.z * b10.w + wB.w * b11.w;
        bestB.x = fmaxf(bestB.x, v.x);
        bestB.y = fmaxf(bestB.y, v.y);
        bestB.z = fmaxf(bestB.z, v.z);
        bestB.w = fmaxf(bestB.w, v.w);
    }

    float4* out4 = (float4*)out;
    out4[(size_t)p * (NCH / 4) + sub]          = bestA;   // batch 0 cell
    out4[(size_t)(NPOS + p) * (NCH / 4) + sub] = bestB;   // batch 1 cell
}

extern "C" void kernel_launch(void* const* d_in, const int* in_sizes, int n_in,
                              void* d_out, int out_size) {
    const float* images = (const float*)d_in[0];
    const float* Ks     = (const float*)d_in[1];
    const float* RTs    = (const float*)d_in[2];
    float* out = (float*)d_out;

    ipm_fused_kernel<<<NBLOCKS, 128>>>(images, Ks, RTs, out);
}

// round 13
// speedup vs baseline: 1.4737x; 1.0226x over previous
#include <cuda_runtime.h>
#include <float.h>
#include <math.h>

// Problem constants (from reference)
#define BEV_N   200          // BEV_H == BEV_W == 200
#define IMG_H   128
#define IMG_W   352
#define NCH     32
#define NB      2            // batch
#define NCAM    6            // cameras per batch
#define BNMAT   (NB*NCAM)    // 12 projection matrices
#define NPOS    (BEV_N*BEV_N)       // 40,000 positions (per batch)
#define POS_PER_BLOCK 16            // 128 threads / 8 lanes-per-position
#define NBLOCKS (NPOS / POS_PER_BLOCK)   // 2500
#define ROWSTRIDE (IMG_W * (NCH/4))
#define GRID_STEP 0.50251256281407031975f   // 100/199 rounded to fp32

// One fused kernel. Each thread owns ONE position but BOTH batches' cells.
// Work mapping: warp w of block b covers positions 4*(w*NBLOCKS + b)..+3.
//  - intra-warp: 4 CONSECUTIVE positions -> gathers within a warp hit adjacent
//    image lines (the locality that R9 showed is essential)
//  - inter-warp: a block's 4 warps are spread across the BEV -> block duration
//    ~= mean work, no straggler blocks in the single-wave launch
__global__ __launch_bounds__(128) void ipm_fused_kernel(const float* __restrict__ images,
                                                        const float* __restrict__ Ks,
                                                        const float* __restrict__ RTs,
                                                        float* __restrict__ out) {
    __shared__ float  sP[BNMAT][9];
    __shared__ float4 sW[POS_PER_BLOCK][NB][NCAM];    // (w00,w01,w10,w11)
    __shared__ int    sBase[POS_PER_BLOCK][NB][NCAM]; // float4-index of im00 (pixel base)

    const int t = threadIdx.x;

    // ---------- Phase 0: projection matrices ----------
    if (t < BNMAT * 9) {
        const int m  = t / 9;
        const int e  = t - m * 9;
        const int r  = e / 3;
        const int ci = e - r * 3;
        const int c  = (ci == 2) ? 3 : ci;
        const float* K  = Ks  + m * 16 + r * 4;
        const float* RT = RTs + m * 16;
        sP[m][e] = K[0] * RT[c] + K[1] * RT[4 + c]
                 + K[2] * RT[8 + c] + K[3] * RT[12 + c];
    }
    __syncthreads();

    const int pos  = t >> 3;                           // local position slot 0..15
    const int sub  = t & 7;                            // lane-in-position / cam slot
    const int warp = t >> 5;                           // warp-in-block 0..3
    const int lpos = (t >> 3) & 3;                     // position-in-warp 0..3

    // Balanced warp-task mapping: 4 consecutive positions per warp,
    // warps of one block spread stride-NBLOCKS across the BEV.
    const int p = (warp * NBLOCKS + blockIdx.x) * 4 + lpos;

    const int i = p / BEV_N;
    const int j = p - i * BEV_N;
    // linspace(-50,50,200) in fp32 (<=1 ulp vs numpy's f64->f32; NO fp64 pipe)
    const float y = fmaf((float)i, GRID_STEP, -50.0f);
    const float x = fmaf((float)j, GRID_STEP, -50.0f);

    // ---------- Phase 1: project both batches + warp-local compaction ----------
    int nA, nB;
    {
        const int cam = sub;                           // cams 0..5 active, 6..7 idle
        bool vA = false, vB = false;
        float4 wA = make_float4(0.f, 0.f, 0.f, 0.f), wB = wA;
        int bA = 0, bB = 0;

        if (cam < NCAM) {
            #pragma unroll
            for (int ba = 0; ba < NB; ba++) {
                const int bn = ba * NCAM + cam;
                const float* P = sP[bn];
                const float pc0 = P[0] * y + P[1] * x + P[2];
                const float pc1 = P[3] * y + P[4] * x + P[5];
                const float pc2 = P[6] * y + P[7] * x + P[8];
                const float inv = 1.0f / (pc2 + 1e-7f);
                const float fx = pc0 * inv;
                const float fy = pc1 * inv;
                // Outside [0,W-1) x [0,H-1): clamped bilinear collapses => exact 0
                if (fx >= 0.0f && fx < (float)(IMG_W - 1) &&
                    fy >= 0.0f && fy < (float)(IMG_H - 1)) {
                    const float x0f = floorf(fx);
                    const float y0f = floorf(fy);
                    const float wx1 = fx - x0f, wx0 = 1.0f - wx1;
                    const float wy1 = fy - y0f, wy0 = 1.0f - wy1;
                    const float4 w = make_float4(wx0 * wy0, wx0 * wy1,
                                                 wx1 * wy0, wx1 * wy1);
                    const int base = ((bn * IMG_H + (int)y0f) * IMG_W + (int)x0f) * (NCH / 4);
                    if (ba == 0) { vA = true; wA = w; bA = base; }
                    else         { vB = true; wB = w; bB = base; }
                }
            }
        }

        const unsigned ballA = __ballot_sync(0xFFFFFFFFu, vA);
        const unsigned ballB = __ballot_sync(0xFFFFFFFFu, vB);
        const int laneBase   = (t & 31) & ~7;                   // first lane of 8-group
        const unsigned grpA  = (ballA >> laneBase) & 0xFFu;
        const unsigned grpB  = (ballB >> laneBase) & 0xFFu;
        const unsigned below = (1u << sub) - 1u;
        if (vA) {
            const int slot = __popc(grpA & below);              // cam-ordered slot
            sW[pos][0][slot] = wA;  sBase[pos][0][slot] = bA;
        }
        if (vB) {
            const int slot = __popc(grpB & below);
            sW[pos][1][slot] = wB;  sBase[pos][1][slot] = bB;
        }
        nA = (int)__popc(grpA);
        nB = (int)__popc(grpB);
    }
    __syncwarp();   // phase 1 writes / phase 2 reads are warp-local (same positions)

    // ---------- Phase 2: branchless paired sampling, max-reduce ----------
    // If every cam is valid the result is max over the 6 samples; otherwise some
    // cam contributes an exact 0 (clamp-collapsed weights), so seed with 0.
    float4 bestA = (nA == NCAM)
        ? make_float4(-FLT_MAX, -FLT_MAX, -FLT_MAX, -FLT_MAX)
        : make_float4(0.f, 0.f, 0.f, 0.f);
    float4 bestB = (nB == NCAM)
        ? make_float4(-FLT_MAX, -FLT_MAX, -FLT_MAX, -FLT_MAX)
        : make_float4(0.f, 0.f, 0.f, 0.f);

    const float4* __restrict__ img4 = (const float4*)images;
    const int nmax = (nA > nB) ? nA : nB;
    const float4 zero4 = make_float4(0.f, 0.f, 0.f, 0.f);

    #pragma unroll 1
    for (int k = 0; k < nmax; k++) {
        const bool okA = (k < nA), okB = (k < nB);
        const int  kA  = okA ? k : 0, kB = okB ? k : 0;
        // Inactive side: weight := 0 (exact-zero contribution), base := 0 (safe addr)
        float4 wA = sW[pos][0][kA];  int baA = okA ? sBase[pos][0][kA] : 0;
        float4 wB = sW[pos][1][kB];  int baB = okB ? sBase[pos][1][kB] : 0;
        if (!okA) wA = zero4;
        if (!okB) wB = zero4;

        const float4* pa = img4 + baA + sub;
        const float4* pb = img4 + baB + sub;
        // 8 independent loads in flight before any consume
        const float4 a00 = __ldg(pa);
        const float4 a10 = __ldg(pa + (NCH / 4));
        const float4 a01 = __ldg(pa + ROWSTRIDE);
        const float4 a11 = __ldg(pa + ROWSTRIDE + (NCH / 4));
        const float4 b00 = __ldg(pb);
        const float4 b10 = __ldg(pb + (NCH / 4));
        const float4 b01 = __ldg(pb + ROWSTRIDE);
        const float4 b11 = __ldg(pb + ROWSTRIDE + (NCH / 4));

        float4 v;
        v.x = wA.x * a00.x + wA.y * a01.x + wA.z * a10.x + wA.w * a11.x;
        v.y = wA.x * a00.y + wA.y * a01.y + wA.z * a10.y + wA.w * a11.y;
        v.z = wA.x * a00.z + wA.y * a01.z + wA.z * a10.z + wA.w * a11.z;
        v.w = wA.x * a00.w + wA.y * a01.w + wA.z * a10.w + wA.w * a11.w;
        bestA.x = fmaxf(bestA.x, v.x);
        bestA.y = fmaxf(bestA.y, v.y);
        bestA.z = fmaxf(bestA.z, v.z);
        bestA.w = fmaxf(bestA.w, v.w);

        v.x = wB.x * b00.x + wB.y * b01.x + wB.z * b10.x + wB.w * b11.x;
        v.y = wB.x * b00.y + wB.y * b01.y + wB.z * b10.y + wB.w * b11.y;
        v.z = wB.x * b00.z + wB.y * b01.z + wB.z * b10.z + wB.w * b11.z;
        v.w = wB.x * b00.w + wB.y * b01.w + wB.z * b10.w + wB.w * b11.w;
        bestB.x = fmaxf(bestB.x, v.x);
        bestB.y = fmaxf(bestB.y, v.y);
        bestB.z = fmaxf(bestB.z, v.z);
        bestB.w = fmaxf(bestB.w, v.w);
    }

    float4* out4 = (float4*)out;
    out4[(size_t)p * (NCH / 4) + sub]          = bestA;   // batch 0 cell
    out4[(size_t)(NPOS + p) * (NCH / 4) + sub] = bestB;   // batch 1 cell
}

extern "C" void kernel_launch(void* const* d_in, const int* in_sizes, int n_in,
                              void* d_out, int out_size) {
    const float* images = (const float*)d_in[0];
    const float* Ks     = (const float*)d_in[1];
    const float* RTs    = (const float*)d_in[2];
    float* out = (float*)d_out;

    ipm_fused_kernel<<<NBLOCKS, 128>>>(images, Ks, RTs, out);
}